// round 7
// baseline (speedup 1.0000x reference)
#include <cuda_runtime.h>

// Problem constants
#define BB      8
#define DIN     1024
#define TT      2048
#define KCB     8192
#define CD      8
#define NTOK    (BB*TT)            // 16384
#define NSPLIT  37
#define CPS     222                // codes per split (37*222 = 8214 >= 8192, padded)
#define KPAD    (NSPLIT*CPS)       // 8214
#define TOKBLK  1024               // tokens per search CTA (256 thr * 4 tok)

// Output buffer layout (float32, concatenated tuple)
#define OUT_OFF   0
#define LOSS_OFF  (BB*DIN*TT)                 // 16777216
#define IDX_OFF   (LOSS_OFF + 16)             // 16777232
#define ZE_OFF    (IDX_OFF + NTOK)            // 16793616

// Scratch (device globals — no allocation allowed)
__device__ float              g_enc[(size_t)NTOK*CD];  // normalized encodings, token-major
__device__ unsigned long long g_cbdup[(size_t)KPAD*9]; // per code: 8x {c,c} + {-c2/2,-c2/2}
__device__ unsigned long long g_wdup[(size_t)DIN*9];   // per out-row: 8x {w,w} + {b,b}
__device__ unsigned long long g_part[NSPLIT*NTOK];     // packed (score_bits<<32)|idx
__device__ int                g_idx[NTOK];

// ---- packed f32x2 helpers ----
__device__ __forceinline__ unsigned long long pack2(float lo, float hi) {
    unsigned long long r;
    asm("mov.b64 %0, {%1,%2};" : "=l"(r) : "f"(lo), "f"(hi));
    return r;
}
__device__ __forceinline__ void unpack2(unsigned long long v, float& lo, float& hi) {
    asm("mov.b64 {%0,%1}, %2;" : "=f"(lo), "=f"(hi) : "l"(v));
}
__device__ __forceinline__ unsigned long long fma2(unsigned long long a, unsigned long long b,
                                                   unsigned long long c) {
    unsigned long long d;
    asm("fma.rn.f32x2 %0, %1, %2, %3;" : "=l"(d) : "l"(a), "l"(b), "l"(c));
    return d;
}
__device__ __forceinline__ unsigned long long add2(unsigned long long a, unsigned long long b) {
    unsigned long long d;
    asm("add.rn.f32x2 %0, %1, %2;" : "=l"(d) : "l"(a), "l"(b));
    return d;
}

// ---------------------------------------------------------------------------
// K0: prep — normalize codebook into duplicated-pair table (padded with
//     sentinel codes that can never win), pack w_out/b_out, zero losses.
// ---------------------------------------------------------------------------
__global__ void k_prep(const float* __restrict__ cb, const float* __restrict__ w_out,
                       const float* __restrict__ b_out, float* __restrict__ out) {
    int i = blockIdx.x * 256 + threadIdx.x;
    if (i < KCB) {
        float v[CD];
#pragma unroll
        for (int k = 0; k < CD; k++) v[k] = cb[(size_t)i * CD + k];
        float s = 0.0f;
#pragma unroll
        for (int k = 0; k < CD; k++) s += v[k] * v[k];
        float den = fmaxf(__fsqrt_rn(s), 1e-12f);
        float nv[CD];
#pragma unroll
        for (int k = 0; k < CD; k++) nv[k] = __fdiv_rn(v[k], den);
        float c2 = 0.0f;
#pragma unroll
        for (int k = 0; k < CD; k++) c2 += nv[k] * nv[k];
#pragma unroll
        for (int k = 0; k < CD; k++) g_cbdup[(size_t)i * 9 + k] = pack2(nv[k], nv[k]);
        float h = -0.5f * c2;
        g_cbdup[(size_t)i * 9 + 8] = pack2(h, h);
    } else if (i < KPAD) {
        // sentinel pad: score accumulates to -1e30, always loses to any real code
#pragma unroll
        for (int k = 0; k < CD; k++) g_cbdup[(size_t)i * 9 + k] = 0ull;
        g_cbdup[(size_t)i * 9 + 8] = pack2(-1e30f, -1e30f);
    } else if (i < KPAD + DIN) {
        int o = i - KPAD;
#pragma unroll
        for (int k = 0; k < CD; k++) {
            float w = w_out[(size_t)o * CD + k];
            g_wdup[(size_t)o * 9 + k] = pack2(w, w);
        }
        float bo = b_out[o];
        g_wdup[(size_t)o * 9 + 8] = pack2(bo, bo);
    } else if (i < KPAD + DIN + 16) {
        out[LOSS_OFF + (i - KPAD - DIN)] = 0.0f;
    }
}

// ---------------------------------------------------------------------------
// K1 (fused): in-projection + bias + z_e store + L2-normalize into g_enc.
// grid (T/64, B), 256 threads.  CTA = 64 tokens x full D=1024.
// ---------------------------------------------------------------------------
__global__ void __launch_bounds__(256) k_inproj(const float* __restrict__ z,
                                                const float* __restrict__ w_in,
                                                const float* __restrict__ b_in,
                                                float* __restrict__ out) {
    __shared__ float sw[DIN * 8];                       // [d][o]  32 KB
    __shared__ unsigned long long sred[256][4];         // per-thread partials  8 KB

    int tid = threadIdx.x;
    for (int i = tid; i < DIN * 8; i += 256) {
        int o = i >> 10, d = i & 1023;
        sw[d * 8 + o] = w_in[i];
    }
    __syncthreads();

    int tok = tid & 63, seg = tid >> 6;
    int b = blockIdx.y;
    int t = blockIdx.x * 64 + tok;

    unsigned long long a01 = 0, a23 = 0, a45 = 0, a67 = 0;
    const float* zp = z + ((size_t)b * DIN + (size_t)seg * 256) * TT + t;
#pragma unroll 4
    for (int dd = 0; dd < 256; dd++) {
        float zv = zp[(size_t)dd * TT];
        unsigned long long zd = pack2(zv, zv);
        const ulonglong2* wp = reinterpret_cast<const ulonglong2*>(&sw[(seg * 256 + dd) * 8]);
        ulonglong2 wA = wp[0], wB = wp[1];
        a01 = fma2(zd, wA.x, a01);
        a23 = fma2(zd, wA.y, a23);
        a45 = fma2(zd, wB.x, a45);
        a67 = fma2(zd, wB.y, a67);
    }
    sred[tid][0] = a01; sred[tid][1] = a23; sred[tid][2] = a45; sred[tid][3] = a67;
    __syncthreads();

    if (tid < 64) {
        float ze[8];
#pragma unroll
        for (int o = 0; o < 8; o++) ze[o] = 0.0f;
#pragma unroll
        for (int s = 0; s < 4; s++) {
#pragma unroll
            for (int p = 0; p < 4; p++) {
                float lo, hi;
                unpack2(sred[tid + 64 * s][p], lo, hi);
                ze[2 * p] += lo;
                ze[2 * p + 1] += hi;
            }
        }
#pragma unroll
        for (int o = 0; o < 8; o++) ze[o] += b_in[o];
#pragma unroll
        for (int o = 0; o < 8; o++)
            out[ZE_OFF + ((size_t)b * 8 + o) * TT + t] = ze[o];
        float s2 = 0.0f;
#pragma unroll
        for (int o = 0; o < 8; o++) s2 += ze[o] * ze[o];
        float den = fmaxf(__fsqrt_rn(s2), 1e-12f);
        int token = b * TT + t;
        float4* ep = reinterpret_cast<float4*>(&g_enc[(size_t)token * 8]);
        float4 e0, e1;
        e0.x = __fdiv_rn(ze[0], den); e0.y = __fdiv_rn(ze[1], den);
        e0.z = __fdiv_rn(ze[2], den); e0.w = __fdiv_rn(ze[3], den);
        e1.x = __fdiv_rn(ze[4], den); e1.y = __fdiv_rn(ze[5], den);
        e1.z = __fdiv_rn(ze[6], den); e1.w = __fdiv_rn(ze[7], den);
        ep[0] = e0; ep[1] = e1;
    }
}

// ---------------------------------------------------------------------------
// K3: nearest-code search.  grid(16 token-blocks, 37 code-splits) = 592 CTAs
// = exactly one full wave at 4 CTAs/SM.  256 thr, 4 tokens/thread, 222 codes.
// score = dot(enc_n, cb_n) - 0.5*c2  (argmax == reference argmin of dist)
// Pad codes (j >= real count in last split) score -1e30 and sit AFTER real
// codes, so they never update best.  fmaxf + change-detect keeps strict-
// improve (first-index-wins) tie semantics.
// ---------------------------------------------------------------------------
__global__ void __launch_bounds__(256, 4) k_search() {
    __shared__ unsigned long long s_cd[CPS][8];
    __shared__ unsigned long long s_c2[CPS];
    int tid = threadIdx.x;
    int cbase = blockIdx.y * CPS;

    for (int i = tid; i < CPS * 9; i += 256) {
        unsigned long long v = g_cbdup[(size_t)cbase * 9 + i];
        int j = i / 9, kk = i - j * 9;
        if (kk < 8) s_cd[j][kk] = v; else s_c2[j] = v;
    }

    int tok0 = blockIdx.x * TOKBLK + tid * 4;
    const float4* ep = reinterpret_cast<const float4*>(&g_enc[(size_t)tok0 * 8]);
    float4 p0 = ep[0], p1 = ep[1], p2 = ep[2], p3 = ep[3];
    float4 p4 = ep[4], p5 = ep[5], p6 = ep[6], p7 = ep[7];
    unsigned long long ea[8], eb[8];
    ea[0] = pack2(p0.x, p2.x); ea[1] = pack2(p0.y, p2.y);
    ea[2] = pack2(p0.z, p2.z); ea[3] = pack2(p0.w, p2.w);
    ea[4] = pack2(p1.x, p3.x); ea[5] = pack2(p1.y, p3.y);
    ea[6] = pack2(p1.z, p3.z); ea[7] = pack2(p1.w, p3.w);
    eb[0] = pack2(p4.x, p6.x); eb[1] = pack2(p4.y, p6.y);
    eb[2] = pack2(p4.z, p6.z); eb[3] = pack2(p4.w, p6.w);
    eb[4] = pack2(p5.x, p7.x); eb[5] = pack2(p5.y, p7.y);
    eb[6] = pack2(p5.z, p7.z); eb[7] = pack2(p5.w, p7.w);

    __syncthreads();

    float best0 = -3.4e38f, best1 = -3.4e38f, best2 = -3.4e38f, best3 = -3.4e38f;
    int bi0 = 0, bi1 = 0, bi2 = 0, bi3 = 0;

#pragma unroll 2
    for (int j = 0; j < CPS; j++) {
        unsigned long long c2p = s_c2[j];
        const ulonglong2* cp = reinterpret_cast<const ulonglong2*>(&s_cd[j][0]);
        ulonglong2 cA = cp[0], cB = cp[1], cC = cp[2], cD = cp[3];

        unsigned long long aA = fma2(ea[0], cA.x, c2p);
        unsigned long long aB = fma2(eb[0], cA.x, c2p);
        aA = fma2(ea[1], cA.y, aA);  aB = fma2(eb[1], cA.y, aB);
        aA = fma2(ea[2], cB.x, aA);  aB = fma2(eb[2], cB.x, aB);
        aA = fma2(ea[3], cB.y, aA);  aB = fma2(eb[3], cB.y, aB);
        aA = fma2(ea[4], cC.x, aA);  aB = fma2(eb[4], cC.x, aB);
        aA = fma2(ea[5], cC.y, aA);  aB = fma2(eb[5], cC.y, aB);
        aA = fma2(ea[6], cD.x, aA);  aB = fma2(eb[6], cD.x, aB);
        aA = fma2(ea[7], cD.y, aA);  aB = fma2(eb[7], cD.y, aB);

        float s0, s1, s2, s3;
        unpack2(aA, s0, s1);
        unpack2(aB, s2, s3);
        float n0 = fmaxf(best0, s0);
        float n1 = fmaxf(best1, s1);
        float n2 = fmaxf(best2, s2);
        float n3 = fmaxf(best3, s3);
        if (n0 != best0) bi0 = j;
        if (n1 != best1) bi1 = j;
        if (n2 != best2) bi2 = j;
        if (n3 != best3) bi3 = j;
        best0 = n0; best1 = n1; best2 = n2; best3 = n3;
    }

    int base = blockIdx.y * NTOK + tok0;
    g_part[base + 0] = ((unsigned long long)__float_as_uint(best0) << 32) | (unsigned)bi0;
    g_part[base + 1] = ((unsigned long long)__float_as_uint(best1) << 32) | (unsigned)bi1;
    g_part[base + 2] = ((unsigned long long)__float_as_uint(best2) << 32) | (unsigned)bi2;
    g_part[base + 3] = ((unsigned long long)__float_as_uint(best3) << 32) | (unsigned)bi3;
}

// ---------------------------------------------------------------------------
// K4: reduce argmax across splits.  2 threads per token (split-halves),
// smem combine.  Ascending split order + strict > keeps first-index ties.
// grid 128 CTAs x 256 thr.
// ---------------------------------------------------------------------------
#define HALF0 19   // splits 0..18
__global__ void __launch_bounds__(256) k_argmin(float* __restrict__ out) {
    __shared__ float s_best[128];
    __shared__ int   s_bi[128];
    int tid = threadIdx.x;
    int lt = tid & 127;            // token slot within block
    int g  = tid >> 7;             // half selector
    int token = blockIdx.x * 128 + lt;

    int s0 = g ? HALF0 : 0;
    int s1 = g ? NSPLIT : HALF0;
    float best = -3.4e38f;
    int bi = 0;
    for (int s = s0; s < s1; s++) {
        unsigned long long p = g_part[s * NTOK + token];
        float v = __uint_as_float((unsigned)(p >> 32));
        if (v > best) { best = v; bi = s * CPS + (int)(unsigned)(p & 0xffffffffu); }
    }
    if (g == 0) { s_best[lt] = best; s_bi[lt] = bi; }
    __syncthreads();
    if (g == 1) {
        // higher half only wins strictly (preserves first-index tie rule)
        if (best > s_best[lt]) { s_best[lt] = best; s_bi[lt] = bi; }
        int fbi = (best > __uint_as_float(__float_as_uint(s_best[lt])) ) ? bi : s_bi[lt];
        // note: s_best[lt] already updated above; recompute cleanly:
        fbi = s_bi[lt];
        g_idx[token] = fbi;
        out[IDX_OFF + token] = (float)fbi;
    }
}

// ---------------------------------------------------------------------------
// K5: out-projection.  grid(T/512, B, 16 o-splits of 64), 256 threads,
//     each thread owns 2 tokens packed as f32x2, 64-bit coalesced stores.
// ---------------------------------------------------------------------------
__global__ void __launch_bounds__(256) k_outproj(const float* __restrict__ cb,
                                                 float* __restrict__ out) {
    __shared__ unsigned long long s_w[64][8];
    __shared__ unsigned long long s_b[64];
    int tid = threadIdx.x;
    int ob = blockIdx.z * 64;
    for (int i = tid; i < 64 * 9; i += 256) {
        unsigned long long v = g_wdup[(size_t)ob * 9 + i];
        int j = i / 9, kk = i - j * 9;
        if (kk < 8) s_w[j][kk] = v; else s_b[j] = v;
    }

    int b = blockIdx.y;
    int t0 = blockIdx.x * 512 + tid * 2;
    int tk0 = b * TT + t0;
    int i0 = g_idx[tk0], i1 = g_idx[tk0 + 1];

    unsigned long long zq[8];
#pragma unroll
    for (int k = 0; k < 8; k++) {
        float ze0 = out[ZE_OFF + ((size_t)b * 8 + k) * TT + t0];
        float ze1 = out[ZE_OFF + ((size_t)b * 8 + k) * TT + t0 + 1];
        float q0 = cb[(size_t)i0 * CD + k];
        float q1 = cb[(size_t)i1 * CD + k];
        zq[k] = pack2(ze0 + (q0 - ze0), ze1 + (q1 - ze1));
    }
    __syncthreads();

    float* obase = out + OUT_OFF + ((size_t)b * DIN + ob) * TT + t0;
#pragma unroll 4
    for (int o = 0; o < 64; o++) {
        const ulonglong2* wp = reinterpret_cast<const ulonglong2*>(&s_w[o][0]);
        ulonglong2 wA = wp[0], wB = wp[1], wC = wp[2], wD = wp[3];
        unsigned long long acc = fma2(zq[0], wA.x, 0ull);
        acc = fma2(zq[1], wA.y, acc);
        acc = fma2(zq[2], wB.x, acc);
        acc = fma2(zq[3], wB.y, acc);
        acc = fma2(zq[4], wC.x, acc);
        acc = fma2(zq[5], wC.y, acc);
        acc = fma2(zq[6], wD.x, acc);
        acc = fma2(zq[7], wD.y, acc);
        acc = add2(acc, s_b[o]);
        *reinterpret_cast<unsigned long long*>(&obase[(size_t)o * TT]) = acc;
    }
}

// ---------------------------------------------------------------------------
extern "C" void kernel_launch(void* const* d_in, const int* in_sizes, int n_in,
                              void* d_out, int out_size) {
    const float* z     = (const float*)d_in[0];
    const float* w_in  = (const float*)d_in[1];
    const float* b_in  = (const float*)d_in[2];
    const float* w_out = (const float*)d_in[3];
    const float* b_out = (const float*)d_in[4];
    const float* cb    = (const float*)d_in[5];
    float* out = (float*)d_out;

    k_prep<<<(KPAD + DIN + 16 + 255) / 256, 256>>>(cb, w_out, b_out, out);

    dim3 g1(TT / 64, BB);              // (32, 8) = 256 CTAs
    k_inproj<<<g1, 256>>>(z, w_in, b_in, out);

    dim3 g3(NTOK / TOKBLK, NSPLIT);    // (16, 37) = 592 CTAs = one full wave
    k_search<<<g3, 256>>>();

    k_argmin<<<NTOK / 128, 256>>>(out);

    dim3 g5(TT / 512, BB, DIN / 64);   // (4, 8, 16)
    k_outproj<<<g5, 256>>>(cb, out);
}

// round 8
// speedup vs baseline: 1.0674x; 1.0674x over previous
#include <cuda_runtime.h>

// Problem constants
#define BB      8
#define DIN     1024
#define TT      2048
#define KCB     8192
#define CD      8
#define NTOK    (BB*TT)            // 16384
#define NSPLIT  37
#define CPS     222                // codes per split (37*222 = 8214 >= 8192, padded)
#define KPAD    (NSPLIT*CPS)       // 8214
#define TOKBLK  1024               // tokens per search CTA (256 thr * 4 tok)

// Output buffer layout (float32, concatenated tuple)
#define OUT_OFF   0
#define LOSS_OFF  (BB*DIN*TT)                 // 16777216
#define IDX_OFF   (LOSS_OFF + 16)             // 16777232
#define ZE_OFF    (IDX_OFF + NTOK)            // 16793616

// Scratch (device globals — no allocation allowed)
__device__ float              g_enc[(size_t)NTOK*CD];  // normalized encodings, token-major
__device__ unsigned long long g_cbdup[(size_t)KPAD*9]; // per code: 8x {c,c} + {-c2/2,-c2/2}
__device__ unsigned long long g_wdup[(size_t)DIN*9];   // per out-row: 8x {w,w} + {b,b}
__device__ unsigned long long g_best[NTOK];            // atomicMax key: (mono(score)<<32)|(8191-idx)

// ---- packed f32x2 helpers ----
__device__ __forceinline__ unsigned long long pack2(float lo, float hi) {
    unsigned long long r;
    asm("mov.b64 %0, {%1,%2};" : "=l"(r) : "f"(lo), "f"(hi));
    return r;
}
__device__ __forceinline__ void unpack2(unsigned long long v, float& lo, float& hi) {
    asm("mov.b64 {%0,%1}, %2;" : "=f"(lo), "=f"(hi) : "l"(v));
}
__device__ __forceinline__ unsigned long long fma2(unsigned long long a, unsigned long long b,
                                                   unsigned long long c) {
    unsigned long long d;
    asm("fma.rn.f32x2 %0, %1, %2, %3;" : "=l"(d) : "l"(a), "l"(b), "l"(c));
    return d;
}

// Monotonic key: unsigned compare on result == float compare on score.
// Low 32 bits: 8191 - idx  ->  score ties resolve to SMALLEST index (first-wins).
__device__ __forceinline__ unsigned long long mkkey(float s, int gidx) {
    unsigned u = __float_as_uint(s);
    unsigned m = u ^ ((unsigned)((int)u >> 31) | 0x80000000u);
    return ((unsigned long long)m << 32) | (unsigned)(KCB - 1 - gidx);
}

// ---------------------------------------------------------------------------
// K0: prep — normalize codebook into duplicated-pair table (padded with
//     sentinel codes that can never win), pack w_out/b_out, zero losses,
//     zero g_best (every call — graph replay safe).
// ---------------------------------------------------------------------------
__global__ void k_prep(const float* __restrict__ cb, const float* __restrict__ w_out,
                       const float* __restrict__ b_out, float* __restrict__ out) {
    int i = blockIdx.x * 256 + threadIdx.x;
    if (i < KCB) {
        float v[CD];
#pragma unroll
        for (int k = 0; k < CD; k++) v[k] = cb[(size_t)i * CD + k];
        float s = 0.0f;
#pragma unroll
        for (int k = 0; k < CD; k++) s += v[k] * v[k];
        float den = fmaxf(__fsqrt_rn(s), 1e-12f);
        float nv[CD];
#pragma unroll
        for (int k = 0; k < CD; k++) nv[k] = __fdiv_rn(v[k], den);
        float c2 = 0.0f;
#pragma unroll
        for (int k = 0; k < CD; k++) c2 += nv[k] * nv[k];
#pragma unroll
        for (int k = 0; k < CD; k++) g_cbdup[(size_t)i * 9 + k] = pack2(nv[k], nv[k]);
        float h = -0.5f * c2;
        g_cbdup[(size_t)i * 9 + 8] = pack2(h, h);
    } else if (i < KPAD) {
        // sentinel pad: score accumulates to -1e30, always loses to any real code
#pragma unroll
        for (int k = 0; k < CD; k++) g_cbdup[(size_t)i * 9 + k] = 0ull;
        g_cbdup[(size_t)i * 9 + 8] = pack2(-1e30f, -1e30f);
    } else if (i < KPAD + DIN) {
        int o = i - KPAD;
#pragma unroll
        for (int k = 0; k < CD; k++) {
            float w = w_out[(size_t)o * CD + k];
            g_wdup[(size_t)o * 9 + k] = pack2(w, w);
        }
        float bo = b_out[o];
        g_wdup[(size_t)o * 9 + 8] = pack2(bo, bo);
    } else if (i < KPAD + DIN + 16) {
        out[LOSS_OFF + (i - KPAD - DIN)] = 0.0f;
    } else if (i < KPAD + DIN + 16 + NTOK) {
        g_best[i - KPAD - DIN - 16] = 0ull;   // below any real key
    }
}

// ---------------------------------------------------------------------------
// K1 (fused): in-projection + bias + z_e store + L2-normalize into g_enc.
// grid (T/64, B), 256 threads.  CTA = 64 tokens x full D=1024.
// ---------------------------------------------------------------------------
__global__ void __launch_bounds__(256) k_inproj(const float* __restrict__ z,
                                                const float* __restrict__ w_in,
                                                const float* __restrict__ b_in,
                                                float* __restrict__ out) {
    __shared__ float sw[DIN * 8];                       // [d][o]  32 KB
    __shared__ unsigned long long sred[256][4];         // per-thread partials  8 KB

    int tid = threadIdx.x;
    for (int i = tid; i < DIN * 8; i += 256) {
        int o = i >> 10, d = i & 1023;
        sw[d * 8 + o] = w_in[i];
    }
    __syncthreads();

    int tok = tid & 63, seg = tid >> 6;
    int b = blockIdx.y;
    int t = blockIdx.x * 64 + tok;

    unsigned long long a01 = 0, a23 = 0, a45 = 0, a67 = 0;
    const float* zp = z + ((size_t)b * DIN + (size_t)seg * 256) * TT + t;
#pragma unroll 4
    for (int dd = 0; dd < 256; dd++) {
        float zv = zp[(size_t)dd * TT];
        unsigned long long zd = pack2(zv, zv);
        const ulonglong2* wp = reinterpret_cast<const ulonglong2*>(&sw[(seg * 256 + dd) * 8]);
        ulonglong2 wA = wp[0], wB = wp[1];
        a01 = fma2(zd, wA.x, a01);
        a23 = fma2(zd, wA.y, a23);
        a45 = fma2(zd, wB.x, a45);
        a67 = fma2(zd, wB.y, a67);
    }
    sred[tid][0] = a01; sred[tid][1] = a23; sred[tid][2] = a45; sred[tid][3] = a67;
    __syncthreads();

    if (tid < 64) {
        float ze[8];
#pragma unroll
        for (int o = 0; o < 8; o++) ze[o] = 0.0f;
#pragma unroll
        for (int s = 0; s < 4; s++) {
#pragma unroll
            for (int p = 0; p < 4; p++) {
                float lo, hi;
                unpack2(sred[tid + 64 * s][p], lo, hi);
                ze[2 * p] += lo;
                ze[2 * p + 1] += hi;
            }
        }
#pragma unroll
        for (int o = 0; o < 8; o++) ze[o] += b_in[o];
#pragma unroll
        for (int o = 0; o < 8; o++)
            out[ZE_OFF + ((size_t)b * 8 + o) * TT + t] = ze[o];
        float s2 = 0.0f;
#pragma unroll
        for (int o = 0; o < 8; o++) s2 += ze[o] * ze[o];
        float den = fmaxf(__fsqrt_rn(s2), 1e-12f);
        int token = b * TT + t;
        float4* ep = reinterpret_cast<float4*>(&g_enc[(size_t)token * 8]);
        float4 e0, e1;
        e0.x = __fdiv_rn(ze[0], den); e0.y = __fdiv_rn(ze[1], den);
        e0.z = __fdiv_rn(ze[2], den); e0.w = __fdiv_rn(ze[3], den);
        e1.x = __fdiv_rn(ze[4], den); e1.y = __fdiv_rn(ze[5], den);
        e1.z = __fdiv_rn(ze[6], den); e1.w = __fdiv_rn(ze[7], den);
        ep[0] = e0; ep[1] = e1;
    }
}

// ---------------------------------------------------------------------------
// K3: nearest-code search.  grid(16 token-blocks, 37 code-splits) = 592 CTAs
// = exactly one full wave at 4 CTAs/SM.  256 thr, 4 tokens/thread, 222 codes.
// score = dot(enc_n, cb_n) - 0.5*c2  (argmax == reference argmin of dist)
// Result merged across splits via RED.MAX.U64 on a monotonic (score,idx) key —
// order-independent => deterministic; tie -> smallest index (reference rule).
// ---------------------------------------------------------------------------
__global__ void __launch_bounds__(256, 4) k_search() {
    __shared__ unsigned long long s_cd[CPS][8];
    __shared__ unsigned long long s_c2[CPS];
    int tid = threadIdx.x;
    int cbase = blockIdx.y * CPS;

    for (int i = tid; i < CPS * 9; i += 256) {
        unsigned long long v = g_cbdup[(size_t)cbase * 9 + i];
        int j = i / 9, kk = i - j * 9;
        if (kk < 8) s_cd[j][kk] = v; else s_c2[j] = v;
    }

    int tok0 = blockIdx.x * TOKBLK + tid * 4;
    const float4* ep = reinterpret_cast<const float4*>(&g_enc[(size_t)tok0 * 8]);
    float4 p0 = ep[0], p1 = ep[1], p2 = ep[2], p3 = ep[3];
    float4 p4 = ep[4], p5 = ep[5], p6 = ep[6], p7 = ep[7];
    unsigned long long ea[8], eb[8];
    ea[0] = pack2(p0.x, p2.x); ea[1] = pack2(p0.y, p2.y);
    ea[2] = pack2(p0.z, p2.z); ea[3] = pack2(p0.w, p2.w);
    ea[4] = pack2(p1.x, p3.x); ea[5] = pack2(p1.y, p3.y);
    ea[6] = pack2(p1.z, p3.z); ea[7] = pack2(p1.w, p3.w);
    eb[0] = pack2(p4.x, p6.x); eb[1] = pack2(p4.y, p6.y);
    eb[2] = pack2(p4.z, p6.z); eb[3] = pack2(p4.w, p6.w);
    eb[4] = pack2(p5.x, p7.x); eb[5] = pack2(p5.y, p7.y);
    eb[6] = pack2(p5.z, p7.z); eb[7] = pack2(p5.w, p7.w);

    __syncthreads();

    float best0 = -3.4e38f, best1 = -3.4e38f, best2 = -3.4e38f, best3 = -3.4e38f;
    int bi0 = 0, bi1 = 0, bi2 = 0, bi3 = 0;

#pragma unroll 2
    for (int j = 0; j < CPS; j++) {
        unsigned long long c2p = s_c2[j];
        const ulonglong2* cp = reinterpret_cast<const ulonglong2*>(&s_cd[j][0]);
        ulonglong2 cA = cp[0], cB = cp[1], cC = cp[2], cD = cp[3];

        unsigned long long aA = fma2(ea[0], cA.x, c2p);
        unsigned long long aB = fma2(eb[0], cA.x, c2p);
        aA = fma2(ea[1], cA.y, aA);  aB = fma2(eb[1], cA.y, aB);
        aA = fma2(ea[2], cB.x, aA);  aB = fma2(eb[2], cB.x, aB);
        aA = fma2(ea[3], cB.y, aA);  aB = fma2(eb[3], cB.y, aB);
        aA = fma2(ea[4], cC.x, aA);  aB = fma2(eb[4], cC.x, aB);
        aA = fma2(ea[5], cC.y, aA);  aB = fma2(eb[5], cC.y, aB);
        aA = fma2(ea[6], cD.x, aA);  aB = fma2(eb[6], cD.x, aB);
        aA = fma2(ea[7], cD.y, aA);  aB = fma2(eb[7], cD.y, aB);

        float s0, s1, s2, s3;
        unpack2(aA, s0, s1);
        unpack2(aB, s2, s3);
        float n0 = fmaxf(best0, s0);
        float n1 = fmaxf(best1, s1);
        float n2 = fmaxf(best2, s2);
        float n3 = fmaxf(best3, s3);
        if (n0 != best0) bi0 = j;
        if (n1 != best1) bi1 = j;
        if (n2 != best2) bi2 = j;
        if (n3 != best3) bi3 = j;
        best0 = n0; best1 = n1; best2 = n2; best3 = n3;
    }

    atomicMax(&g_best[tok0 + 0], mkkey(best0, cbase + bi0));
    atomicMax(&g_best[tok0 + 1], mkkey(best1, cbase + bi1));
    atomicMax(&g_best[tok0 + 2], mkkey(best2, cbase + bi2));
    atomicMax(&g_best[tok0 + 3], mkkey(best3, cbase + bi3));
}

// ---------------------------------------------------------------------------
// K5: out-projection.  grid(T/1024, B, 32 o-splits of 32), 256 threads,
//     each thread owns 4 tokens (two f32x2 pairs), STG.128 stores, bias
//     folded into fma chain init.  Decodes indices from g_best; z-slice 0
//     also writes the indices output.
//     z_q_st = z_e + (codebook[idx] - z_e)  (exact straight-through value)
// ---------------------------------------------------------------------------
__global__ void __launch_bounds__(256) k_outproj(const float* __restrict__ cb,
                                                 float* __restrict__ out) {
    __shared__ unsigned long long s_w[32][8];
    __shared__ unsigned long long s_b[32];
    int tid = threadIdx.x;
    int ob = blockIdx.z * 32;
    for (int i = tid; i < 32 * 9; i += 256) {
        unsigned long long v = g_wdup[(size_t)ob * 9 + i];
        int j = i / 9, kk = i - j * 9;
        if (kk < 8) s_w[j][kk] = v; else s_b[j] = v;
    }

    int b = blockIdx.y;
    int t0 = blockIdx.x * 1024 + tid * 4;
    int tk = b * TT + t0;

    unsigned long long pk0 = g_best[tk], pk1 = g_best[tk + 1];
    unsigned long long pk2 = g_best[tk + 2], pk3 = g_best[tk + 3];
    int i0 = KCB - 1 - (int)(unsigned)(pk0 & 0xffffffffu);
    int i1 = KCB - 1 - (int)(unsigned)(pk1 & 0xffffffffu);
    int i2 = KCB - 1 - (int)(unsigned)(pk2 & 0xffffffffu);
    int i3 = KCB - 1 - (int)(unsigned)(pk3 & 0xffffffffu);

    if (blockIdx.z == 0) {
        float4 iv;
        iv.x = (float)i0; iv.y = (float)i1; iv.z = (float)i2; iv.w = (float)i3;
        *reinterpret_cast<float4*>(&out[IDX_OFF + tk]) = iv;
    }

    float q0[8], q1[8], q2[8], q3[8];
    {
        const float4* c;
        c = reinterpret_cast<const float4*>(cb + (size_t)i0 * 8);
        *reinterpret_cast<float4*>(&q0[0]) = c[0]; *reinterpret_cast<float4*>(&q0[4]) = c[1];
        c = reinterpret_cast<const float4*>(cb + (size_t)i1 * 8);
        *reinterpret_cast<float4*>(&q1[0]) = c[0]; *reinterpret_cast<float4*>(&q1[4]) = c[1];
        c = reinterpret_cast<const float4*>(cb + (size_t)i2 * 8);
        *reinterpret_cast<float4*>(&q2[0]) = c[0]; *reinterpret_cast<float4*>(&q2[4]) = c[1];
        c = reinterpret_cast<const float4*>(cb + (size_t)i3 * 8);
        *reinterpret_cast<float4*>(&q3[0]) = c[0]; *reinterpret_cast<float4*>(&q3[4]) = c[1];
    }

    unsigned long long zqA[8], zqB[8];
#pragma unroll
    for (int k = 0; k < 8; k++) {
        float4 ze = *reinterpret_cast<const float4*>(&out[ZE_OFF + ((size_t)b * 8 + k) * TT + t0]);
        zqA[k] = pack2(ze.x + (q0[k] - ze.x), ze.y + (q1[k] - ze.y));
        zqB[k] = pack2(ze.z + (q2[k] - ze.z), ze.w + (q3[k] - ze.w));
    }
    __syncthreads();

    float* obase = out + OUT_OFF + ((size_t)b * DIN + ob) * TT + t0;
#pragma unroll 2
    for (int o = 0; o < 32; o++) {
        const ulonglong2* wp = reinterpret_cast<const ulonglong2*>(&s_w[o][0]);
        ulonglong2 wA = wp[0], wB = wp[1], wC = wp[2], wD = wp[3];
        unsigned long long bias = s_b[o];
        unsigned long long aA = fma2(zqA[0], wA.x, bias);
        unsigned long long aB = fma2(zqB[0], wA.x, bias);
        aA = fma2(zqA[1], wA.y, aA);  aB = fma2(zqB[1], wA.y, aB);
        aA = fma2(zqA[2], wB.x, aA);  aB = fma2(zqB[2], wB.x, aB);
        aA = fma2(zqA[3], wB.y, aA);  aB = fma2(zqB[3], wB.y, aB);
        aA = fma2(zqA[4], wC.x, aA);  aB = fma2(zqB[4], wC.x, aB);
        aA = fma2(zqA[5], wC.y, aA);  aB = fma2(zqB[5], wC.y, aB);
        aA = fma2(zqA[6], wD.x, aA);  aB = fma2(zqB[6], wD.x, aB);
        aA = fma2(zqA[7], wD.y, aA);  aB = fma2(zqB[7], wD.y, aB);
        ulonglong2 st; st.x = aA; st.y = aB;
        *reinterpret_cast<ulonglong2*>(&obase[(size_t)o * TT]) = st;
    }
}

// ---------------------------------------------------------------------------
extern "C" void kernel_launch(void* const* d_in, const int* in_sizes, int n_in,
                              void* d_out, int out_size) {
    const float* z     = (const float*)d_in[0];
    const float* w_in  = (const float*)d_in[1];
    const float* b_in  = (const float*)d_in[2];
    const float* w_out = (const float*)d_in[3];
    const float* b_out = (const float*)d_in[4];
    const float* cb    = (const float*)d_in[5];
    float* out = (float*)d_out;

    k_prep<<<(KPAD + DIN + 16 + NTOK + 255) / 256, 256>>>(cb, w_out, b_out, out);

    dim3 g1(TT / 64, BB);              // (32, 8) = 256 CTAs
    k_inproj<<<g1, 256>>>(z, w_in, b_in, out);

    dim3 g3(NTOK / TOKBLK, NSPLIT);    // (16, 37) = 592 CTAs = one full wave
    k_search<<<g3, 256>>>();

    dim3 g5(TT / 1024, BB, DIN / 32);  // (2, 8, 32) = 512 CTAs
    k_outproj<<<g5, 256>>>(cb, out);
}

// round 9
// speedup vs baseline: 1.1179x; 1.0472x over previous
#include <cuda_runtime.h>

// Problem constants
#define BB      8
#define DIN     1024
#define TT      2048
#define KCB     8192
#define CD      8
#define NTOK    (BB*TT)            // 16384
#define NSPLIT  37
#define CPS     222                // codes per split (37*222 = 8214 >= 8192, padded)
#define KPAD    (NSPLIT*CPS)       // 8214
#define TOKBLK  1024               // tokens per search CTA (256 thr * 4 tok)

// Output buffer layout (float32, concatenated tuple)
#define OUT_OFF   0
#define LOSS_OFF  (BB*DIN*TT)                 // 16777216
#define IDX_OFF   (LOSS_OFF + 16)             // 16777232
#define ZE_OFF    (IDX_OFF + NTOK)            // 16793616

// Scratch (device globals — no allocation allowed)
__device__ float              g_enc[(size_t)NTOK*CD];  // normalized encodings, token-major
__device__ unsigned long long g_cbdup[(size_t)KPAD*9]; // per code: 8x {c,c} + {-c2/2,-c2/2}
__device__ unsigned long long g_wdup[(size_t)DIN*9];   // per out-row: 8x {w,w} + {b,b}
__device__ unsigned long long g_best[NTOK];            // atomicMax key: (mono(score)<<32)|(8191-idx)

// ---- packed f32x2 helpers ----
__device__ __forceinline__ unsigned long long pack2(float lo, float hi) {
    unsigned long long r;
    asm("mov.b64 %0, {%1,%2};" : "=l"(r) : "f"(lo), "f"(hi));
    return r;
}
__device__ __forceinline__ void unpack2(unsigned long long v, float& lo, float& hi) {
    asm("mov.b64 {%0,%1}, %2;" : "=f"(lo), "=f"(hi) : "l"(v));
}
__device__ __forceinline__ unsigned long long fma2(unsigned long long a, unsigned long long b,
                                                   unsigned long long c) {
    unsigned long long d;
    asm("fma.rn.f32x2 %0, %1, %2, %3;" : "=l"(d) : "l"(a), "l"(b), "l"(c));
    return d;
}
__device__ __forceinline__ unsigned long long add2(unsigned long long a, unsigned long long b) {
    unsigned long long d;
    asm("add.rn.f32x2 %0, %1, %2;" : "=l"(d) : "l"(a), "l"(b));
    return d;
}

// Monotonic key: unsigned compare on result == float compare on score.
// Low 32 bits: 8191 - idx  ->  score ties resolve to SMALLEST index (first-wins).
__device__ __forceinline__ unsigned long long mkkey(float s, int gidx) {
    unsigned u = __float_as_uint(s);
    unsigned m = u ^ ((unsigned)((int)u >> 31) | 0x80000000u);
    return ((unsigned long long)m << 32) | (unsigned)(KCB - 1 - gidx);
}

// ---------------------------------------------------------------------------
// K0: prep — normalize codebook into duplicated-pair table (padded with
//     sentinel codes that can never win), pack w_out/b_out, zero losses,
//     zero g_best (every call — graph replay safe).
// ---------------------------------------------------------------------------
__global__ void k_prep(const float* __restrict__ cb, const float* __restrict__ w_out,
                       const float* __restrict__ b_out, float* __restrict__ out) {
    int i = blockIdx.x * 256 + threadIdx.x;
    if (i < KCB) {
        float v[CD];
#pragma unroll
        for (int k = 0; k < CD; k++) v[k] = cb[(size_t)i * CD + k];
        float s = 0.0f;
#pragma unroll
        for (int k = 0; k < CD; k++) s += v[k] * v[k];
        float den = fmaxf(__fsqrt_rn(s), 1e-12f);
        float nv[CD];
#pragma unroll
        for (int k = 0; k < CD; k++) nv[k] = __fdiv_rn(v[k], den);
        float c2 = 0.0f;
#pragma unroll
        for (int k = 0; k < CD; k++) c2 += nv[k] * nv[k];
#pragma unroll
        for (int k = 0; k < CD; k++) g_cbdup[(size_t)i * 9 + k] = pack2(nv[k], nv[k]);
        float h = -0.5f * c2;
        g_cbdup[(size_t)i * 9 + 8] = pack2(h, h);
    } else if (i < KPAD) {
        // sentinel pad: score accumulates to -1e30, always loses to any real code
#pragma unroll
        for (int k = 0; k < CD; k++) g_cbdup[(size_t)i * 9 + k] = 0ull;
        g_cbdup[(size_t)i * 9 + 8] = pack2(-1e30f, -1e30f);
    } else if (i < KPAD + DIN) {
        int o = i - KPAD;
#pragma unroll
        for (int k = 0; k < CD; k++) {
            float w = w_out[(size_t)o * CD + k];
            g_wdup[(size_t)o * 9 + k] = pack2(w, w);
        }
        float bo = b_out[o];
        g_wdup[(size_t)o * 9 + 8] = pack2(bo, bo);
    } else if (i < KPAD + DIN + 16) {
        out[LOSS_OFF + (i - KPAD - DIN)] = 0.0f;
    } else if (i < KPAD + DIN + 16 + NTOK) {
        g_best[i - KPAD - DIN - 16] = 0ull;   // below any real key
    }
}

// ---------------------------------------------------------------------------
// K1 (fused): in-projection + bias + z_e store + L2-normalize into g_enc.
// grid (T/16, B) = 1024 CTAs, 256 threads.  CTA = 16 tokens x full D=1024.
// Warp = 16 tokens x 2 D-segments of 64; shfl_xor(16) folds segments, smem
// stage folds 8 warps, 64-thread tail does bias + normalize.
// ---------------------------------------------------------------------------
__global__ void __launch_bounds__(256) k_inproj(const float* __restrict__ z,
                                                const float* __restrict__ w_in,
                                                const float* __restrict__ b_in,
                                                float* __restrict__ out) {
    __shared__ float sw[DIN * 8];                        // [d][o]  32 KB
    __shared__ unsigned long long sred[8][16][4];        // [warp][tok][pack] 4 KB

    int tid = threadIdx.x;
    for (int i = tid; i < DIN * 8; i += 256) {
        int o = i >> 10, d = i & 1023;
        sw[d * 8 + o] = w_in[i];
    }
    __syncthreads();

    int lane = tid & 31, warp = tid >> 5;
    int tokl = lane & 15;
    int segh = lane >> 4;                 // 0/1
    int seg = warp * 2 + segh;            // 0..15, 64 d each
    int b = blockIdx.y;
    int t = blockIdx.x * 16 + tokl;

    unsigned long long a01 = 0, a23 = 0, a45 = 0, a67 = 0;
    const float* zp = z + ((size_t)b * DIN + (size_t)seg * 64) * TT + t;
    const float* swp = &sw[seg * 64 * 8];
#pragma unroll 4
    for (int dd = 0; dd < 64; dd++) {
        float zv = zp[(size_t)dd * TT];
        unsigned long long zd = pack2(zv, zv);
        const ulonglong2* wp = reinterpret_cast<const ulonglong2*>(&swp[dd * 8]);
        ulonglong2 wA = wp[0], wB = wp[1];
        a01 = fma2(zd, wA.x, a01);
        a23 = fma2(zd, wA.y, a23);
        a45 = fma2(zd, wB.x, a45);
        a67 = fma2(zd, wB.y, a67);
    }
    // fold the two D-segments within the warp
    a01 = add2(a01, __shfl_xor_sync(0xffffffffu, a01, 16));
    a23 = add2(a23, __shfl_xor_sync(0xffffffffu, a23, 16));
    a45 = add2(a45, __shfl_xor_sync(0xffffffffu, a45, 16));
    a67 = add2(a67, __shfl_xor_sync(0xffffffffu, a67, 16));
    if (segh == 0) {
        sred[warp][tokl][0] = a01; sred[warp][tokl][1] = a23;
        sred[warp][tokl][2] = a45; sred[warp][tokl][3] = a67;
    }
    __syncthreads();

    if (tid < 64) {
        int pk = tid & 3;        // channel pair {2pk, 2pk+1}
        int tk = tid >> 2;       // token slot 0..15
        unsigned long long s = sred[0][tk][pk];
#pragma unroll
        for (int w = 1; w < 8; w++) s = add2(s, sred[w][tk][pk]);
        float lo, hi;
        unpack2(s, lo, hi);
        lo += b_in[2 * pk];
        hi += b_in[2 * pk + 1];

        int tt = blockIdx.x * 16 + tk;
        out[ZE_OFF + ((size_t)b * 8 + 2 * pk) * TT + tt]     = lo;
        out[ZE_OFF + ((size_t)b * 8 + 2 * pk + 1) * TT + tt] = hi;

        float s2 = lo * lo + hi * hi;
        s2 += __shfl_xor_sync(0xffffffffu, s2, 1);
        s2 += __shfl_xor_sync(0xffffffffu, s2, 2);
        float den = fmaxf(__fsqrt_rn(s2), 1e-12f);
        int token = b * TT + tt;
        reinterpret_cast<unsigned long long*>(&g_enc[(size_t)token * 8])[pk] =
            pack2(__fdiv_rn(lo, den), __fdiv_rn(hi, den));
    }
}

// ---------------------------------------------------------------------------
// K3: nearest-code search.  grid(16 token-blocks, 37 code-splits) = 592 CTAs
// = exactly one full wave at 4 CTAs/SM.  256 thr, 4 tokens/thread, 222 codes.
// score = dot(enc_n, cb_n) - 0.5*c2  (argmax == reference argmin of dist)
// Result merged across splits via RED.MAX.U64 on a monotonic (score,idx) key —
// order-independent => deterministic; tie -> smallest index (reference rule).
// ---------------------------------------------------------------------------
__global__ void __launch_bounds__(256, 4) k_search() {
    __shared__ unsigned long long s_cd[CPS][8];
    __shared__ unsigned long long s_c2[CPS];
    int tid = threadIdx.x;
    int cbase = blockIdx.y * CPS;

    for (int i = tid; i < CPS * 9; i += 256) {
        unsigned long long v = g_cbdup[(size_t)cbase * 9 + i];
        int j = i / 9, kk = i - j * 9;
        if (kk < 8) s_cd[j][kk] = v; else s_c2[j] = v;
    }

    int tok0 = blockIdx.x * TOKBLK + tid * 4;
    const float4* ep = reinterpret_cast<const float4*>(&g_enc[(size_t)tok0 * 8]);
    float4 p0 = ep[0], p1 = ep[1], p2 = ep[2], p3 = ep[3];
    float4 p4 = ep[4], p5 = ep[5], p6 = ep[6], p7 = ep[7];
    unsigned long long ea[8], eb[8];
    ea[0] = pack2(p0.x, p2.x); ea[1] = pack2(p0.y, p2.y);
    ea[2] = pack2(p0.z, p2.z); ea[3] = pack2(p0.w, p2.w);
    ea[4] = pack2(p1.x, p3.x); ea[5] = pack2(p1.y, p3.y);
    ea[6] = pack2(p1.z, p3.z); ea[7] = pack2(p1.w, p3.w);
    eb[0] = pack2(p4.x, p6.x); eb[1] = pack2(p4.y, p6.y);
    eb[2] = pack2(p4.z, p6.z); eb[3] = pack2(p4.w, p6.w);
    eb[4] = pack2(p5.x, p7.x); eb[5] = pack2(p5.y, p7.y);
    eb[6] = pack2(p5.z, p7.z); eb[7] = pack2(p5.w, p7.w);

    __syncthreads();

    float best0 = -3.4e38f, best1 = -3.4e38f, best2 = -3.4e38f, best3 = -3.4e38f;
    int bi0 = 0, bi1 = 0, bi2 = 0, bi3 = 0;

#pragma unroll 2
    for (int j = 0; j < CPS; j++) {
        unsigned long long c2p = s_c2[j];
        const ulonglong2* cp = reinterpret_cast<const ulonglong2*>(&s_cd[j][0]);
        ulonglong2 cA = cp[0], cB = cp[1], cC = cp[2], cD = cp[3];

        unsigned long long aA = fma2(ea[0], cA.x, c2p);
        unsigned long long aB = fma2(eb[0], cA.x, c2p);
        aA = fma2(ea[1], cA.y, aA);  aB = fma2(eb[1], cA.y, aB);
        aA = fma2(ea[2], cB.x, aA);  aB = fma2(eb[2], cB.x, aB);
        aA = fma2(ea[3], cB.y, aA);  aB = fma2(eb[3], cB.y, aB);
        aA = fma2(ea[4], cC.x, aA);  aB = fma2(eb[4], cC.x, aB);
        aA = fma2(ea[5], cC.y, aA);  aB = fma2(eb[5], cC.y, aB);
        aA = fma2(ea[6], cD.x, aA);  aB = fma2(eb[6], cD.x, aB);
        aA = fma2(ea[7], cD.y, aA);  aB = fma2(eb[7], cD.y, aB);

        float s0, s1, s2, s3;
        unpack2(aA, s0, s1);
        unpack2(aB, s2, s3);
        float n0 = fmaxf(best0, s0);
        float n1 = fmaxf(best1, s1);
        float n2 = fmaxf(best2, s2);
        float n3 = fmaxf(best3, s3);
        if (n0 != best0) bi0 = j;
        if (n1 != best1) bi1 = j;
        if (n2 != best2) bi2 = j;
        if (n3 != best3) bi3 = j;
        best0 = n0; best1 = n1; best2 = n2; best3 = n3;
    }

    atomicMax(&g_best[tok0 + 0], mkkey(best0, cbase + bi0));
    atomicMax(&g_best[tok0 + 1], mkkey(best1, cbase + bi1));
    atomicMax(&g_best[tok0 + 2], mkkey(best2, cbase + bi2));
    atomicMax(&g_best[tok0 + 3], mkkey(best3, cbase + bi3));
}

// ---------------------------------------------------------------------------
// K5: out-projection.  grid(T/1024, B, 64 o-splits of 16) = 1024 CTAs,
//     256 threads, 4 tokens/thread (two f32x2 pairs), STG.128 stores, bias
//     folded into fma chain init.  Decodes indices from g_best; z-slice 0
//     also writes the indices output.
//     z_q_st = z_e + (codebook[idx] - z_e)  (exact straight-through value)
// ---------------------------------------------------------------------------
__global__ void __launch_bounds__(256) k_outproj(const float* __restrict__ cb,
                                                 float* __restrict__ out) {
    __shared__ unsigned long long s_w[16][8];
    __shared__ unsigned long long s_b[16];
    int tid = threadIdx.x;
    int ob = blockIdx.z * 16;
    if (tid < 16 * 9) {
        unsigned long long v = g_wdup[(size_t)ob * 9 + tid];
        int j = tid / 9, kk = tid - j * 9;
        if (kk < 8) s_w[j][kk] = v; else s_b[j] = v;
    }

    int b = blockIdx.y;
    int t0 = blockIdx.x * 1024 + tid * 4;
    int tk = b * TT + t0;

    unsigned long long pk0 = g_best[tk], pk1 = g_best[tk + 1];
    unsigned long long pk2 = g_best[tk + 2], pk3 = g_best[tk + 3];
    int i0 = KCB - 1 - (int)(unsigned)(pk0 & 0xffffffffu);
    int i1 = KCB - 1 - (int)(unsigned)(pk1 & 0xffffffffu);
    int i2 = KCB - 1 - (int)(unsigned)(pk2 & 0xffffffffu);
    int i3 = KCB - 1 - (int)(unsigned)(pk3 & 0xffffffffu);

    if (blockIdx.z == 0) {
        float4 iv;
        iv.x = (float)i0; iv.y = (float)i1; iv.z = (float)i2; iv.w = (float)i3;
        *reinterpret_cast<float4*>(&out[IDX_OFF + tk]) = iv;
    }

    float q0[8], q1[8], q2[8], q3[8];
    {
        const float4* c;
        c = reinterpret_cast<const float4*>(cb + (size_t)i0 * 8);
        *reinterpret_cast<float4*>(&q0[0]) = c[0]; *reinterpret_cast<float4*>(&q0[4]) = c[1];
        c = reinterpret_cast<const float4*>(cb + (size_t)i1 * 8);
        *reinterpret_cast<float4*>(&q1[0]) = c[0]; *reinterpret_cast<float4*>(&q1[4]) = c[1];
        c = reinterpret_cast<const float4*>(cb + (size_t)i2 * 8);
        *reinterpret_cast<float4*>(&q2[0]) = c[0]; *reinterpret_cast<float4*>(&q2[4]) = c[1];
        c = reinterpret_cast<const float4*>(cb + (size_t)i3 * 8);
        *reinterpret_cast<float4*>(&q3[0]) = c[0]; *reinterpret_cast<float4*>(&q3[4]) = c[1];
    }

    unsigned long long zqA[8], zqB[8];
#pragma unroll
    for (int k = 0; k < 8; k++) {
        float4 ze = *reinterpret_cast<const float4*>(&out[ZE_OFF + ((size_t)b * 8 + k) * TT + t0]);
        zqA[k] = pack2(ze.x + (q0[k] - ze.x), ze.y + (q1[k] - ze.y));
        zqB[k] = pack2(ze.z + (q2[k] - ze.z), ze.w + (q3[k] - ze.w));
    }
    __syncthreads();

    float* obase = out + OUT_OFF + ((size_t)b * DIN + ob) * TT + t0;
#pragma unroll 2
    for (int o = 0; o < 16; o++) {
        const ulonglong2* wp = reinterpret_cast<const ulonglong2*>(&s_w[o][0]);
        ulonglong2 wA = wp[0], wB = wp[1], wC = wp[2], wD = wp[3];
        unsigned long long bias = s_b[o];
        unsigned long long aA = fma2(zqA[0], wA.x, bias);
        unsigned long long aB = fma2(zqB[0], wA.x, bias);
        aA = fma2(zqA[1], wA.y, aA);  aB = fma2(zqB[1], wA.y, aB);
        aA = fma2(zqA[2], wB.x, aA);  aB = fma2(zqB[2], wB.x, aB);
        aA = fma2(zqA[3], wB.y, aA);  aB = fma2(zqB[3], wB.y, aB);
        aA = fma2(zqA[4], wC.x, aA);  aB = fma2(zqB[4], wC.x, aB);
        aA = fma2(zqA[5], wC.y, aA);  aB = fma2(zqB[5], wC.y, aB);
        aA = fma2(zqA[6], wD.x, aA);  aB = fma2(zqB[6], wD.x, aB);
        aA = fma2(zqA[7], wD.y, aA);  aB = fma2(zqB[7], wD.y, aB);
        ulonglong2 st; st.x = aA; st.y = aB;
        *reinterpret_cast<ulonglong2*>(&obase[(size_t)o * TT]) = st;
    }
}

// ---------------------------------------------------------------------------
extern "C" void kernel_launch(void* const* d_in, const int* in_sizes, int n_in,
                              void* d_out, int out_size) {
    const float* z     = (const float*)d_in[0];
    const float* w_in  = (const float*)d_in[1];
    const float* b_in  = (const float*)d_in[2];
    const float* w_out = (const float*)d_in[3];
    const float* b_out = (const float*)d_in[4];
    const float* cb    = (const float*)d_in[5];
    float* out = (float*)d_out;

    k_prep<<<(KPAD + DIN + 16 + NTOK + 255) / 256, 256>>>(cb, w_out, b_out, out);

    dim3 g1(TT / 16, BB);              // (128, 8) = 1024 CTAs
    k_inproj<<<g1, 256>>>(z, w_in, b_in, out);

    dim3 g3(NTOK / TOKBLK, NSPLIT);    // (16, 37) = 592 CTAs = one full wave
    k_search<<<g3, 256>>>();

    dim3 g5(TT / 1024, BB, DIN / 16);  // (2, 8, 64) = 1024 CTAs
    k_outproj<<<g5, 256>>>(cb, out);
}

// round 10
// speedup vs baseline: 1.1353x; 1.0156x over previous
#include <cuda_runtime.h>

// Problem constants
#define BB      8
#define DIN     1024
#define TT      2048
#define KCB     8192
#define CD      8
#define NTOK    (BB*TT)            // 16384
#define NSPLIT  37
#define CPS     222                // codes per split (37*222 = 8214 >= 8192, padded)
#define KPAD    (NSPLIT*CPS)       // 8214
#define TOKBLK  1024               // tokens per search CTA (256 thr * 4 tok)

// Output buffer layout (float32, concatenated tuple)
#define OUT_OFF   0
#define LOSS_OFF  (BB*DIN*TT)                 // 16777216
#define IDX_OFF   (LOSS_OFF + 16)             // 16777232
#define ZE_OFF    (IDX_OFF + NTOK)            // 16793616

// Scratch (device globals — no allocation allowed)
__device__ float              g_enc[(size_t)NTOK*CD];  // normalized encodings, token-major
__device__ unsigned long long g_cbdup[(size_t)KPAD*9]; // per code: 8x {c,c} + {-c2/2,-c2/2}
__device__ unsigned long long g_wdup[(size_t)DIN*9];   // per out-row: 8x {w,w} + {b,b}
__device__ unsigned long long g_best[NTOK];            // atomicMax key: (mono(score)<<32)|(8191-idx)

// ---- packed f32x2 helpers ----
__device__ __forceinline__ unsigned long long pack2(float lo, float hi) {
    unsigned long long r;
    asm("mov.b64 %0, {%1,%2};" : "=l"(r) : "f"(lo), "f"(hi));
    return r;
}
__device__ __forceinline__ void unpack2(unsigned long long v, float& lo, float& hi) {
    asm("mov.b64 {%0,%1}, %2;" : "=f"(lo), "=f"(hi) : "l"(v));
}
__device__ __forceinline__ unsigned long long fma2(unsigned long long a, unsigned long long b,
                                                   unsigned long long c) {
    unsigned long long d;
    asm("fma.rn.f32x2 %0, %1, %2, %3;" : "=l"(d) : "l"(a), "l"(b), "l"(c));
    return d;
}
__device__ __forceinline__ unsigned long long add2(unsigned long long a, unsigned long long b) {
    unsigned long long d;
    asm("add.rn.f32x2 %0, %1, %2;" : "=l"(d) : "l"(a), "l"(b));
    return d;
}

// Monotonic key: unsigned compare on result == float compare on score.
// Low 32 bits: 8191 - idx  ->  score ties resolve to SMALLEST index (first-wins).
__device__ __forceinline__ unsigned long long mkkey(float s, int gidx) {
    unsigned u = __float_as_uint(s);
    unsigned m = u ^ ((unsigned)((int)u >> 31) | 0x80000000u);
    return ((unsigned long long)m << 32) | (unsigned)(KCB - 1 - gidx);
}

// ---------------------------------------------------------------------------
// K0: prep — normalize codebook into duplicated-pair table (padded with
//     sentinel codes that can never win), pack w_out/b_out, zero losses,
//     zero g_best (every call — graph replay safe).
// ---------------------------------------------------------------------------
__global__ void k_prep(const float* __restrict__ cb, const float* __restrict__ w_out,
                       const float* __restrict__ b_out, float* __restrict__ out) {
    int i = blockIdx.x * 256 + threadIdx.x;
    if (i < KCB) {
        float v[CD];
#pragma unroll
        for (int k = 0; k < CD; k++) v[k] = cb[(size_t)i * CD + k];
        float s = 0.0f;
#pragma unroll
        for (int k = 0; k < CD; k++) s += v[k] * v[k];
        float den = fmaxf(__fsqrt_rn(s), 1e-12f);
        float nv[CD];
#pragma unroll
        for (int k = 0; k < CD; k++) nv[k] = __fdiv_rn(v[k], den);
        float c2 = 0.0f;
#pragma unroll
        for (int k = 0; k < CD; k++) c2 += nv[k] * nv[k];
#pragma unroll
        for (int k = 0; k < CD; k++) g_cbdup[(size_t)i * 9 + k] = pack2(nv[k], nv[k]);
        float h = -0.5f * c2;
        g_cbdup[(size_t)i * 9 + 8] = pack2(h, h);
    } else if (i < KPAD) {
        // sentinel pad: score accumulates to -1e30, always loses to any real code
#pragma unroll
        for (int k = 0; k < CD; k++) g_cbdup[(size_t)i * 9 + k] = 0ull;
        g_cbdup[(size_t)i * 9 + 8] = pack2(-1e30f, -1e30f);
    } else if (i < KPAD + DIN) {
        int o = i - KPAD;
#pragma unroll
        for (int k = 0; k < CD; k++) {
            float w = w_out[(size_t)o * CD + k];
            g_wdup[(size_t)o * 9 + k] = pack2(w, w);
        }
        float bo = b_out[o];
        g_wdup[(size_t)o * 9 + 8] = pack2(bo, bo);
    } else if (i < KPAD + DIN + 16) {
        out[LOSS_OFF + (i - KPAD - DIN)] = 0.0f;
    } else if (i < KPAD + DIN + 16 + NTOK) {
        g_best[i - KPAD - DIN - 16] = 0ull;   // below any real key
    }
}

// ---------------------------------------------------------------------------
// K1 (fused): in-projection + bias + z_e store + L2-normalize into g_enc.
// grid (T/16, B) = 1024 CTAs, 256 threads.  CTA = 16 tokens x full D=1024.
// Warp = 16 tokens x 2 D-segments of 64; shfl_xor(16) folds segments, smem
// stage folds 8 warps, 64-thread tail does bias + normalize.
// ---------------------------------------------------------------------------
__global__ void __launch_bounds__(256) k_inproj(const float* __restrict__ z,
                                                const float* __restrict__ w_in,
                                                const float* __restrict__ b_in,
                                                float* __restrict__ out) {
    __shared__ float sw[DIN * 8];                        // [d][o]  32 KB
    __shared__ unsigned long long sred[8][16][4];        // [warp][tok][pack] 4 KB

    int tid = threadIdx.x;
    for (int i = tid; i < DIN * 8; i += 256) {
        int o = i >> 10, d = i & 1023;
        sw[d * 8 + o] = w_in[i];
    }
    __syncthreads();

    int lane = tid & 31, warp = tid >> 5;
    int tokl = lane & 15;
    int segh = lane >> 4;                 // 0/1
    int seg = warp * 2 + segh;            // 0..15, 64 d each
    int b = blockIdx.y;
    int t = blockIdx.x * 16 + tokl;

    unsigned long long a01 = 0, a23 = 0, a45 = 0, a67 = 0;
    const float* zp = z + ((size_t)b * DIN + (size_t)seg * 64) * TT + t;
    const float* swp = &sw[seg * 64 * 8];
#pragma unroll 8
    for (int dd = 0; dd < 64; dd++) {
        float zv = zp[(size_t)dd * TT];
        unsigned long long zd = pack2(zv, zv);
        const ulonglong2* wp = reinterpret_cast<const ulonglong2*>(&swp[dd * 8]);
        ulonglong2 wA = wp[0], wB = wp[1];
        a01 = fma2(zd, wA.x, a01);
        a23 = fma2(zd, wA.y, a23);
        a45 = fma2(zd, wB.x, a45);
        a67 = fma2(zd, wB.y, a67);
    }
    // fold the two D-segments within the warp
    a01 = add2(a01, __shfl_xor_sync(0xffffffffu, a01, 16));
    a23 = add2(a23, __shfl_xor_sync(0xffffffffu, a23, 16));
    a45 = add2(a45, __shfl_xor_sync(0xffffffffu, a45, 16));
    a67 = add2(a67, __shfl_xor_sync(0xffffffffu, a67, 16));
    if (segh == 0) {
        sred[warp][tokl][0] = a01; sred[warp][tokl][1] = a23;
        sred[warp][tokl][2] = a45; sred[warp][tokl][3] = a67;
    }
    __syncthreads();

    if (tid < 64) {
        int pk = tid & 3;        // channel pair {2pk, 2pk+1}
        int tk = tid >> 2;       // token slot 0..15
        unsigned long long s = sred[0][tk][pk];
#pragma unroll
        for (int w = 1; w < 8; w++) s = add2(s, sred[w][tk][pk]);
        float lo, hi;
        unpack2(s, lo, hi);
        lo += b_in[2 * pk];
        hi += b_in[2 * pk + 1];

        int tt = blockIdx.x * 16 + tk;
        out[ZE_OFF + ((size_t)b * 8 + 2 * pk) * TT + tt]     = lo;
        out[ZE_OFF + ((size_t)b * 8 + 2 * pk + 1) * TT + tt] = hi;

        float s2 = lo * lo + hi * hi;
        s2 += __shfl_xor_sync(0xffffffffu, s2, 1);
        s2 += __shfl_xor_sync(0xffffffffu, s2, 2);
        float den = fmaxf(__fsqrt_rn(s2), 1e-12f);
        int token = b * TT + tt;
        reinterpret_cast<unsigned long long*>(&g_enc[(size_t)token * 8])[pk] =
            pack2(__fdiv_rn(lo, den), __fdiv_rn(hi, den));
    }
}

// ---------------------------------------------------------------------------
// K3: nearest-code search.  grid(16 token-blocks, 37 code-splits) = 592 CTAs
// = exactly one full wave at 4 CTAs/SM.  256 thr, 4 tokens/thread, 222 codes.
// score = dot(enc_n, cb_n) - 0.5*c2  (argmax == reference argmin of dist)
// Result merged across splits via RED.MAX.U64 on a monotonic (score,idx) key —
// order-independent => deterministic; tie -> smallest index (reference rule).
// FMA-pipe bound at the fp32 floor (~70us); do not touch without a new pipe.
// ---------------------------------------------------------------------------
__global__ void __launch_bounds__(256, 4) k_search() {
    __shared__ unsigned long long s_cd[CPS][8];
    __shared__ unsigned long long s_c2[CPS];
    int tid = threadIdx.x;
    int cbase = blockIdx.y * CPS;

    for (int i = tid; i < CPS * 9; i += 256) {
        unsigned long long v = g_cbdup[(size_t)cbase * 9 + i];
        int j = i / 9, kk = i - j * 9;
        if (kk < 8) s_cd[j][kk] = v; else s_c2[j] = v;
    }

    int tok0 = blockIdx.x * TOKBLK + tid * 4;
    const float4* ep = reinterpret_cast<const float4*>(&g_enc[(size_t)tok0 * 8]);
    float4 p0 = ep[0], p1 = ep[1], p2 = ep[2], p3 = ep[3];
    float4 p4 = ep[4], p5 = ep[5], p6 = ep[6], p7 = ep[7];
    unsigned long long ea[8], eb[8];
    ea[0] = pack2(p0.x, p2.x); ea[1] = pack2(p0.y, p2.y);
    ea[2] = pack2(p0.z, p2.z); ea[3] = pack2(p0.w, p2.w);
    ea[4] = pack2(p1.x, p3.x); ea[5] = pack2(p1.y, p3.y);
    ea[6] = pack2(p1.z, p3.z); ea[7] = pack2(p1.w, p3.w);
    eb[0] = pack2(p4.x, p6.x); eb[1] = pack2(p4.y, p6.y);
    eb[2] = pack2(p4.z, p6.z); eb[3] = pack2(p4.w, p6.w);
    eb[4] = pack2(p5.x, p7.x); eb[5] = pack2(p5.y, p7.y);
    eb[6] = pack2(p5.z, p7.z); eb[7] = pack2(p5.w, p7.w);

    __syncthreads();

    float best0 = -3.4e38f, best1 = -3.4e38f, best2 = -3.4e38f, best3 = -3.4e38f;
    int bi0 = 0, bi1 = 0, bi2 = 0, bi3 = 0;

#pragma unroll 2
    for (int j = 0; j < CPS; j++) {
        unsigned long long c2p = s_c2[j];
        const ulonglong2* cp = reinterpret_cast<const ulonglong2*>(&s_cd[j][0]);
        ulonglong2 cA = cp[0], cB = cp[1], cC = cp[2], cD = cp[3];

        unsigned long long aA = fma2(ea[0], cA.x, c2p);
        unsigned long long aB = fma2(eb[0], cA.x, c2p);
        aA = fma2(ea[1], cA.y, aA);  aB = fma2(eb[1], cA.y, aB);
        aA = fma2(ea[2], cB.x, aA);  aB = fma2(eb[2], cB.x, aB);
        aA = fma2(ea[3], cB.y, aA);  aB = fma2(eb[3], cB.y, aB);
        aA = fma2(ea[4], cC.x, aA);  aB = fma2(eb[4], cC.x, aB);
        aA = fma2(ea[5], cC.y, aA);  aB = fma2(eb[5], cC.y, aB);
        aA = fma2(ea[6], cD.x, aA);  aB = fma2(eb[6], cD.x, aB);
        aA = fma2(ea[7], cD.y, aA);  aB = fma2(eb[7], cD.y, aB);

        float s0, s1, s2, s3;
        unpack2(aA, s0, s1);
        unpack2(aB, s2, s3);
        float n0 = fmaxf(best0, s0);
        float n1 = fmaxf(best1, s1);
        float n2 = fmaxf(best2, s2);
        float n3 = fmaxf(best3, s3);
        if (n0 != best0) bi0 = j;
        if (n1 != best1) bi1 = j;
        if (n2 != best2) bi2 = j;
        if (n3 != best3) bi3 = j;
        best0 = n0; best1 = n1; best2 = n2; best3 = n3;
    }

    atomicMax(&g_best[tok0 + 0], mkkey(best0, cbase + bi0));
    atomicMax(&g_best[tok0 + 1], mkkey(best1, cbase + bi1));
    atomicMax(&g_best[tok0 + 2], mkkey(best2, cbase + bi2));
    atomicMax(&g_best[tok0 + 3], mkkey(best3, cbase + bi3));
}

// ---------------------------------------------------------------------------
// K5: out-projection.  grid(T/512, B, 64 o-splits of 16) = 2048 CTAs,
//     256 threads, 2 tokens/thread (one f32x2 pair) -> ~48 regs, 5 CTAs/SM.
//     STG.64 stores (adjacent threads coalesce to 128B lines), bias folded
//     into fma chain init.  Decodes indices from g_best; z-slice 0 writes
//     the indices output.
//     z_q_st = z_e + (codebook[idx] - z_e)  (exact straight-through value)
// ---------------------------------------------------------------------------
__global__ void __launch_bounds__(256, 5) k_outproj(const float* __restrict__ cb,
                                                    float* __restrict__ out) {
    __shared__ unsigned long long s_w[16][8];
    __shared__ unsigned long long s_b[16];
    int tid = threadIdx.x;
    int ob = blockIdx.z * 16;
    if (tid < 16 * 9) {
        unsigned long long v = g_wdup[(size_t)ob * 9 + tid];
        int j = tid / 9, kk = tid - j * 9;
        if (kk < 8) s_w[j][kk] = v; else s_b[j] = v;
    }

    int b = blockIdx.y;
    int t0 = blockIdx.x * 512 + tid * 2;
    int tk = b * TT + t0;

    unsigned long long pk0 = g_best[tk], pk1 = g_best[tk + 1];
    int i0 = KCB - 1 - (int)(unsigned)(pk0 & 0xffffffffu);
    int i1 = KCB - 1 - (int)(unsigned)(pk1 & 0xffffffffu);

    if (blockIdx.z == 0) {
        float2 iv;
        iv.x = (float)i0; iv.y = (float)i1;
        *reinterpret_cast<float2*>(&out[IDX_OFF + tk]) = iv;
    }

    float q0[8], q1[8];
    {
        const float4* c;
        c = reinterpret_cast<const float4*>(cb + (size_t)i0 * 8);
        *reinterpret_cast<float4*>(&q0[0]) = c[0]; *reinterpret_cast<float4*>(&q0[4]) = c[1];
        c = reinterpret_cast<const float4*>(cb + (size_t)i1 * 8);
        *reinterpret_cast<float4*>(&q1[0]) = c[0]; *reinterpret_cast<float4*>(&q1[4]) = c[1];
    }

    unsigned long long zq[8];
#pragma unroll
    for (int k = 0; k < 8; k++) {
        float2 ze = *reinterpret_cast<const float2*>(&out[ZE_OFF + ((size_t)b * 8 + k) * TT + t0]);
        zq[k] = pack2(ze.x + (q0[k] - ze.x), ze.y + (q1[k] - ze.y));
    }
    __syncthreads();

    float* obase = out + OUT_OFF + ((size_t)b * DIN + ob) * TT + t0;
#pragma unroll 4
    for (int o = 0; o < 16; o++) {
        const ulonglong2* wp = reinterpret_cast<const ulonglong2*>(&s_w[o][0]);
        ulonglong2 wA = wp[0], wB = wp[1], wC = wp[2], wD = wp[3];
        unsigned long long acc = fma2(zq[0], wA.x, s_b[o]);
        acc = fma2(zq[1], wA.y, acc);
        acc = fma2(zq[2], wB.x, acc);
        acc = fma2(zq[3], wB.y, acc);
        acc = fma2(zq[4], wC.x, acc);
        acc = fma2(zq[5], wC.y, acc);
        acc = fma2(zq[6], wD.x, acc);
        acc = fma2(zq[7], wD.y, acc);
        *reinterpret_cast<unsigned long long*>(&obase[(size_t)o * TT]) = acc;
    }
}

// ---------------------------------------------------------------------------
extern "C" void kernel_launch(void* const* d_in, const int* in_sizes, int n_in,
                              void* d_out, int out_size) {
    const float* z     = (const float*)d_in[0];
    const float* w_in  = (const float*)d_in[1];
    const float* b_in  = (const float*)d_in[2];
    const float* w_out = (const float*)d_in[3];
    const float* b_out = (const float*)d_in[4];
    const float* cb    = (const float*)d_in[5];
    float* out = (float*)d_out;

    k_prep<<<(KPAD + DIN + 16 + NTOK + 255) / 256, 256>>>(cb, w_out, b_out, out);

    dim3 g1(TT / 16, BB);              // (128, 8) = 1024 CTAs
    k_inproj<<<g1, 256>>>(z, w_in, b_in, out);

    dim3 g3(NTOK / TOKBLK, NSPLIT);    // (16, 37) = 592 CTAs = one full wave
    k_search<<<g3, 256>>>();

    dim3 g5(TT / 512, BB, DIN / 16);   // (4, 8, 64) = 2048 CTAs
    k_outproj<<<g5, 256>>>(cb, out);
}